// round 15
// baseline (speedup 1.0000x reference)
#include <cuda_runtime.h>
#include <stdint.h>
#include <math.h>

#define BATCH 32
#define CHAN  256
#define HH    56
#define WW    56
#define S     (HH*WW)        // 3136
#define S4    (S/4)          // 784
#define QSPLIT 8
#define CQ    (CHAN/QSPLIT)  // 32
#define RNUM  1568           // removed_num = round(3136*0.5)
#define FSCALE 1048576.0f    // 2^20 fixed-point scale for deterministic sum

// scratch (no cudaMalloc allowed). Zero-init == atomic identities:
// fkey(f) > 0 for every finite f, so 0 is below all max keys; sum starts 0.
// fused_mid reads then re-zeros -> replay-safe.
__device__ unsigned int       g_kmax[BATCH*S];
__device__ unsigned long long g_fsum[BATCH*S];
__device__ __align__(16) float g_y[BATCH*S];

// monotone float->uint key (standard order-preserving map)
__device__ __forceinline__ unsigned int fkey(float f) {
    unsigned int b = __float_as_uint(f);
    return (b & 0x80000000u) ? ~b : (b | 0x80000000u);
}
__device__ __forceinline__ float fval(unsigned int k) {
    unsigned int b = (k & 0x80000000u) ? (k & 0x7FFFFFFFu) : ~k;
    return __uint_as_float(b);
}

// ---------------------------------------------------------------------------
// Kernel 1: channel max/sum merged directly into final pooled arrays via
// deterministic atomics. 784 blocks x 256 threads (measured-best shape).
// atomicMax(uint key): exact & commutative. atomicAdd(u64 fixed-point):
// associative mod 2^64 -> bit-deterministic; |sum32|<2^8 so 2^20 scale fits.
// ---------------------------------------------------------------------------
__global__ void pool_partial(const float* __restrict__ x) {
    int gid = blockIdx.x * blockDim.x + threadIdx.x;
    int q   = gid / (BATCH * S4);
    int rem = gid % (BATCH * S4);
    int b   = rem / S4;
    int s4  = rem % S4;

    const float4* p = reinterpret_cast<const float4*>(x)
                    + (size_t)(b * CHAN + q * CQ) * S4 + s4;

    float4 mx = make_float4(-INFINITY, -INFINITY, -INFINITY, -INFINITY);
    float4 sm = make_float4(0.f, 0.f, 0.f, 0.f);

    #pragma unroll 8
    for (int c = 0; c < CQ; ++c) {
        float4 v = __ldcs(p + (size_t)c * S4);   // read-once: stream past L2
        mx.x = fmaxf(mx.x, v.x); mx.y = fmaxf(mx.y, v.y);
        mx.z = fmaxf(mx.z, v.z); mx.w = fmaxf(mx.w, v.w);
        sm.x += v.x; sm.y += v.y; sm.z += v.z; sm.w += v.w;
    }

    int s0 = b * S + s4 * 4;
    atomicMax(&g_kmax[s0 + 0], fkey(mx.x));
    atomicMax(&g_kmax[s0 + 1], fkey(mx.y));
    atomicMax(&g_kmax[s0 + 2], fkey(mx.z));
    atomicMax(&g_kmax[s0 + 3], fkey(mx.w));
    atomicAdd(&g_fsum[s0 + 0], (unsigned long long)(long long)llrintf(sm.x * FSCALE));
    atomicAdd(&g_fsum[s0 + 1], (unsigned long long)(long long)llrintf(sm.y * FSCALE));
    atomicAdd(&g_fsum[s0 + 2], (unsigned long long)(long long)llrintf(sm.z * FSCALE));
    atomicAdd(&g_fsum[s0 + 3], (unsigned long long)(long long)llrintf(sm.w * FSCALE));
}

// ---------------------------------------------------------------------------
// Kernel 2 (fused middle): load pooled max/avg (37.6KB/batch, then reset for
// next replay), conv+sigmoid with fused pass-0 histogram, exact radix select,
// masked write with merged tie collection. One block per batch, 1024 threads.
// ---------------------------------------------------------------------------
__global__ void __launch_bounds__(1024, 1) fused_mid(const float* __restrict__ w) {
    __shared__ float pm[S];
    __shared__ float pa[S];
    __shared__ unsigned int uvals[S];     // sigmoid bits; >0 so uint order == float order
    __shared__ int hist[256];
    __shared__ float ws[18];
    __shared__ unsigned int s_prefix;
    __shared__ int s_r, s_less;
    __shared__ int tieIdx[256];
    __shared__ int tieCount;

    const int b = blockIdx.x;
    const int t = threadIdx.x;
    const int lane = t & 31;

    if (t < 18) ws[t] = w[t];
    if (t < 256) hist[t] = 0;             // pre-clear for fused pass 0
    if (t == 0) { s_r = RNUM - 1; s_less = 0; s_prefix = 0u; tieCount = 0; }

    // --- load pooled values, reset accumulators for next replay ---
    const float cvt = (1.0f / FSCALE) * (1.0f / (float)CHAN);
    for (int i = t; i < S; i += 1024) {
        unsigned int k       = g_kmax[b * S + i];
        unsigned long long f = g_fsum[b * S + i];
        g_kmax[b * S + i] = 0u;
        g_fsum[b * S + i] = 0ull;
        pm[i] = fval(k);
        pa[i] = __ll2float_rn((long long)f) * cvt;
    }
    __syncthreads();

    // --- conv 3x3 (2ch->1ch, pad 1, cross-corr OIHW) + sigmoid + pass-0 hist ---
    for (int i = t; i < S; i += 1024) {
        int oh = i / WW, ow = i % WW;
        float acc = 0.f;
        #pragma unroll
        for (int ky = 0; ky < 3; ++ky) {
            int ih = oh + ky - 1;
            if (ih < 0 || ih >= HH) continue;
            #pragma unroll
            for (int kx = 0; kx < 3; ++kx) {
                int iw = ow + kx - 1;
                if (iw < 0 || iw >= WW) continue;
                int ii = ih * WW + iw;
                acc = fmaf(pm[ii], ws[ky * 3 + kx], acc);
                acc = fmaf(pa[ii], ws[9 + ky * 3 + kx], acc);
            }
        }
        unsigned int u = __float_as_uint(1.0f / (1.0f + expf(-acc)));
        uvals[i] = u;
        atomicAdd(&hist[u >> 24], 1);      // fused radix pass 0
    }
    __syncthreads();

    // --- 4-pass radix select (pass 0 histogram already built) ---
    #pragma unroll
    for (int pass = 0; pass < 4; ++pass) {
        const int shift = 24 - 8 * pass;

        if (pass > 0) {
            const unsigned int pmask = 0xFFFFFFFFu << (32 - 8 * pass);
            const unsigned int pref  = s_prefix;
            for (int i = t; i < S; i += 1024) {
                unsigned int u = uvals[i];
                if ((u & pmask) == pref)
                    atomicAdd(&hist[(u >> shift) & 0xFF], 1);
            }
            __syncthreads();
        }

        if (t < 32) {                      // warp-0 bin scan + select
            int base = t * 8;
            int h0 = hist[base + 0], h1 = hist[base + 1];
            int h2 = hist[base + 2], h3 = hist[base + 3];
            int h4 = hist[base + 4], h5 = hist[base + 5];
            int h6 = hist[base + 6], h7 = hist[base + 7];
            int tot = h0 + h1 + h2 + h3 + h4 + h5 + h6 + h7;

            int ex = tot;                  // -> exclusive prefix of lane totals
            #pragma unroll
            for (int d = 1; d < 32; d <<= 1) {
                int n = __shfl_up_sync(0xFFFFFFFFu, ex, d);
                if (lane >= d) ex += n;
            }
            ex -= tot;

            int r = s_r;
            if (ex <= r && r < ex + tot) { // exactly one lane matches
                int cum = ex, bin = base;
                int hh[8] = {h0,h1,h2,h3,h4,h5,h6,h7};
                #pragma unroll
                for (int k = 0; k < 8; ++k) {
                    if (cum + hh[k] > r) { bin = base + k; break; }
                    cum += hh[k];
                }
                s_r      = r - cum;
                s_less  += cum;
                s_prefix = (pass == 0 ? 0u : s_prefix) | ((unsigned int)bin << shift);
            }
        }
        __syncthreads();

        if (pass < 3) {                    // clear for next pass
            if (t < 256) hist[t] = 0;
            __syncthreads();
        }
    }

    const unsigned int T = s_prefix;
    const int zeroTies = RNUM - s_less;    // # ties (==T) to zero, ascending index

    // --- merged masked write + tie collection (single sweep) ---
    float* yb = g_y + b * S;
    for (int i = t; i < S; i += 1024) {
        unsigned int u = uvals[i];
        float v = __uint_as_float(u);
        if (u < T) v = 0.0f;
        else if (u == T) {
            int p = atomicAdd(&tieCount, 1);
            if (p < 256) tieIdx[p] = i;
        }
        yb[i] = v;                         // ties fixed below
    }
    __syncthreads();

    if (t == 0) {
        int tc = tieCount < 256 ? tieCount : 256;
        for (int i = 1; i < tc; ++i) {     // expected tc == 1
            int v2 = tieIdx[i], j = i - 1;
            while (j >= 0 && tieIdx[j] > v2) { tieIdx[j + 1] = tieIdx[j]; --j; }
            tieIdx[j + 1] = v2;
        }
        int z = zeroTies < tc ? zeroTies : tc;
        for (int j = 0; j < z; ++j) yb[tieIdx[j]] = 0.0f;
    }
}

// ---------------------------------------------------------------------------
// Kernel 3: broadcast masked map to all 256 channels. (Measured best: 16.0us)
// 1 float4 load -> 8 streaming (__stcs) stores; 1568 blocks x 512 threads.
// ---------------------------------------------------------------------------
__global__ void __launch_bounds__(512) bcast(float* __restrict__ out) {
    int gid  = blockIdx.x * 512 + threadIdx.x;    // 0 .. BATCH*32*S4-1
    int s4   = gid % S4;
    int rowg = gid / S4;                          // b*32 + cg
    int b    = rowg >> 5;
    int cg   = rowg & 31;

    float4 v = __ldg(reinterpret_cast<const float4*>(g_y) + b * S4 + s4);

    float4* p = reinterpret_cast<float4*>(out)
              + ((size_t)(b * CHAN + cg * 8)) * S4 + s4;
    #pragma unroll
    for (int k = 0; k < 8; ++k) {
        __stcs(p, v);                      // evict-first: don't churn L2
        p += S4;
    }
}

// ---------------------------------------------------------------------------
extern "C" void kernel_launch(void* const* d_in, const int* in_sizes, int n_in,
                              void* d_out, int out_size) {
    const float* x = (const float*)d_in[0];   // [32,256,56,56]
    const float* w = (const float*)d_in[1];   // [1,2,3,3]
    float* out = (float*)d_out;               // [32,256,56,56]

    pool_partial<<<(QSPLIT * BATCH * S4) / 256, 256>>>(x);   // 784 blocks
    fused_mid<<<BATCH, 1024>>>(w);                           // 32 blocks
    bcast<<<(BATCH * 32 * S4) / 512, 512>>>(out);            // 1568 blocks
}

// round 16
// speedup vs baseline: 1.1642x; 1.1642x over previous
#include <cuda_runtime.h>
#include <stdint.h>
#include <math.h>

#define BATCH 32
#define CHAN  256
#define HH    56
#define WW    56
#define S     (HH*WW)        // 3136
#define S4    (S/4)          // 784
#define QSPLIT 8
#define CQ    (CHAN/QSPLIT)  // 32
#define RNUM  1568           // removed_num = round(3136*0.5)

// scratch (no cudaMalloc allowed)
__device__ __align__(16) float g_part_max[QSPLIT*BATCH*S];
__device__ __align__(16) float g_part_sum[QSPLIT*BATCH*S];
__device__ __align__(16) float g_y[BATCH*S];

// ---------------------------------------------------------------------------
// Kernel 1: partial channel max/sum. 784 blocks x 256 threads, QSPLIT=8.
// (Measured best: 19.3us @ 70% DRAM — do not touch.)
// ---------------------------------------------------------------------------
__global__ void pool_partial(const float* __restrict__ x) {
    int gid = blockIdx.x * blockDim.x + threadIdx.x;
    int q   = gid / (BATCH * S4);
    int rem = gid % (BATCH * S4);
    int b   = rem / S4;
    int s4  = rem % S4;

    const float4* p = reinterpret_cast<const float4*>(x)
                    + (size_t)(b * CHAN + q * CQ) * S4 + s4;

    float4 mx = make_float4(-INFINITY, -INFINITY, -INFINITY, -INFINITY);
    float4 sm = make_float4(0.f, 0.f, 0.f, 0.f);

    #pragma unroll 8
    for (int c = 0; c < CQ; ++c) {
        float4 v = __ldcs(p + (size_t)c * S4);   // read-once: stream past L2
        mx.x = fmaxf(mx.x, v.x); mx.y = fmaxf(mx.y, v.y);
        mx.z = fmaxf(mx.z, v.z); mx.w = fmaxf(mx.w, v.w);
        sm.x += v.x; sm.y += v.y; sm.z += v.z; sm.w += v.w;
    }

    int o = (q * BATCH + b) * S4 + s4;
    reinterpret_cast<float4*>(g_part_max)[o] = mx;
    reinterpret_cast<float4*>(g_part_sum)[o] = sm;
}

// ---------------------------------------------------------------------------
// Kernel 2 (fused middle): combine partials, conv+sigmoid (pass-0 histogram
// fused), exact radix select (2 barriers/pass: warp 0 clears bins during its
// scan), masked write with merged tie collection. 1 block/batch, 1024 thr.
// ---------------------------------------------------------------------------
__global__ void __launch_bounds__(1024, 1) fused_mid(const float* __restrict__ w) {
    __shared__ float pm[S];
    __shared__ float pa[S];
    __shared__ unsigned int uvals[S];     // sigmoid bits; >0 so uint order == float order
    __shared__ int hist[256];
    __shared__ float ws[18];
    __shared__ unsigned int s_prefix;
    __shared__ int s_r, s_less;
    __shared__ int tieIdx[256];
    __shared__ int tieCount;

    const int b = blockIdx.x;
    const int t = threadIdx.x;
    const int lane = t & 31;

    if (t < 18) ws[t] = w[t];
    if (t < 256) hist[t] = 0;             // pre-clear for fused pass 0
    if (t == 0) { s_r = RNUM - 1; s_less = 0; s_prefix = 0u; tieCount = 0; }

    // --- combine QSPLIT partials -> pooled max/avg in smem (float4/thread) ---
    const float inv = 1.0f / (float)CHAN;
    if (t < S4) {
        float4 mx = make_float4(-INFINITY, -INFINITY, -INFINITY, -INFINITY);
        float4 sm = make_float4(0.f, 0.f, 0.f, 0.f);
        #pragma unroll
        for (int q = 0; q < QSPLIT; ++q) {
            int o = (q * BATCH + b) * S4 + t;
            float4 m = reinterpret_cast<const float4*>(g_part_max)[o];
            float4 s = reinterpret_cast<const float4*>(g_part_sum)[o];
            mx.x = fmaxf(mx.x, m.x); mx.y = fmaxf(mx.y, m.y);
            mx.z = fmaxf(mx.z, m.z); mx.w = fmaxf(mx.w, m.w);
            sm.x += s.x; sm.y += s.y; sm.z += s.z; sm.w += s.w;
        }
        sm.x *= inv; sm.y *= inv; sm.z *= inv; sm.w *= inv;
        reinterpret_cast<float4*>(pm)[t] = mx;
        reinterpret_cast<float4*>(pa)[t] = sm;
    }
    __syncthreads();

    // --- conv 3x3 (2ch->1ch, pad 1, cross-corr OIHW) + sigmoid + pass-0 hist ---
    for (int i = t; i < S; i += 1024) {
        int oh = i / WW, ow = i % WW;
        float acc = 0.f;
        #pragma unroll
        for (int ky = 0; ky < 3; ++ky) {
            int ih = oh + ky - 1;
            if (ih < 0 || ih >= HH) continue;
            #pragma unroll
            for (int kx = 0; kx < 3; ++kx) {
                int iw = ow + kx - 1;
                if (iw < 0 || iw >= WW) continue;
                int ii = ih * WW + iw;
                acc = fmaf(pm[ii], ws[ky * 3 + kx], acc);
                acc = fmaf(pa[ii], ws[9 + ky * 3 + kx], acc);
            }
        }
        unsigned int u = __float_as_uint(1.0f / (1.0f + expf(-acc)));
        uvals[i] = u;
        atomicAdd(&hist[u >> 24], 1);      // fused radix pass 0
    }
    __syncthreads();

    // --- 4-pass radix select, 2 barriers/pass (warp 0 clears bins in scan) ---
    #pragma unroll
    for (int pass = 0; pass < 4; ++pass) {
        const int shift = 24 - 8 * pass;

        if (pass > 0) {
            const unsigned int pmask = 0xFFFFFFFFu << (32 - 8 * pass);
            const unsigned int pref  = s_prefix;
            for (int i = t; i < S; i += 1024) {
                unsigned int u = uvals[i];
                if ((u & pmask) == pref)
                    atomicAdd(&hist[(u >> shift) & 0xFF], 1);
            }
            __syncthreads();
        }

        if (t < 32) {                      // warp-0 bin scan + select + clear
            int base = t * 8;
            int h0 = hist[base + 0], h1 = hist[base + 1];
            int h2 = hist[base + 2], h3 = hist[base + 3];
            int h4 = hist[base + 4], h5 = hist[base + 5];
            int h6 = hist[base + 6], h7 = hist[base + 7];
            // clear for next pass (only warp 0 touches hist between barriers)
            hist[base + 0] = 0; hist[base + 1] = 0;
            hist[base + 2] = 0; hist[base + 3] = 0;
            hist[base + 4] = 0; hist[base + 5] = 0;
            hist[base + 6] = 0; hist[base + 7] = 0;

            int tot = h0 + h1 + h2 + h3 + h4 + h5 + h6 + h7;
            int ex = tot;                  // -> exclusive prefix of lane totals
            #pragma unroll
            for (int d = 1; d < 32; d <<= 1) {
                int n = __shfl_up_sync(0xFFFFFFFFu, ex, d);
                if (lane >= d) ex += n;
            }
            ex -= tot;

            int r = s_r;
            if (ex <= r && r < ex + tot) { // exactly one lane matches
                int cum = ex, bin = base;
                int hh[8] = {h0,h1,h2,h3,h4,h5,h6,h7};
                #pragma unroll
                for (int k = 0; k < 8; ++k) {
                    if (cum + hh[k] > r) { bin = base + k; break; }
                    cum += hh[k];
                }
                s_r      = r - cum;
                s_less  += cum;
                s_prefix = (pass == 0 ? 0u : s_prefix) | ((unsigned int)bin << shift);
            }
        }
        __syncthreads();
    }

    const unsigned int T = s_prefix;
    const int zeroTies = RNUM - s_less;    // # ties (==T) to zero, ascending index

    // --- merged masked write + tie collection (single sweep) ---
    float* yb = g_y + b * S;
    for (int i = t; i < S; i += 1024) {
        unsigned int u = uvals[i];
        float v = __uint_as_float(u);
        if (u < T) v = 0.0f;
        else if (u == T) {
            int p = atomicAdd(&tieCount, 1);
            if (p < 256) tieIdx[p] = i;
        }
        yb[i] = v;                         // ties fixed below
    }
    __syncthreads();

    if (t == 0) {
        int tc = tieCount < 256 ? tieCount : 256;
        for (int i = 1; i < tc; ++i) {     // expected tc == 1
            int v2 = tieIdx[i], j = i - 1;
            while (j >= 0 && tieIdx[j] > v2) { tieIdx[j + 1] = tieIdx[j]; --j; }
            tieIdx[j + 1] = v2;
        }
        int z = zeroTies < tc ? zeroTies : tc;
        for (int j = 0; j < z; ++j) yb[tieIdx[j]] = 0.0f;
    }
}

// ---------------------------------------------------------------------------
// Kernel 3: broadcast masked map to all 256 channels. (Measured best: 16.0us)
// 1 float4 load -> 8 streaming (__stcs) stores; 1568 blocks x 512 threads.
// ---------------------------------------------------------------------------
__global__ void __launch_bounds__(512) bcast(float* __restrict__ out) {
    int gid  = blockIdx.x * 512 + threadIdx.x;    // 0 .. BATCH*32*S4-1
    int s4   = gid % S4;
    int rowg = gid / S4;                          // b*32 + cg
    int b    = rowg >> 5;
    int cg   = rowg & 31;

    float4 v = __ldg(reinterpret_cast<const float4*>(g_y) + b * S4 + s4);

    float4* p = reinterpret_cast<float4*>(out)
              + ((size_t)(b * CHAN + cg * 8)) * S4 + s4;
    #pragma unroll
    for (int k = 0; k < 8; ++k) {
        __stcs(p, v);                      // evict-first: don't churn L2
        p += S4;
    }
}

// ---------------------------------------------------------------------------
extern "C" void kernel_launch(void* const* d_in, const int* in_sizes, int n_in,
                              void* d_out, int out_size) {
    const float* x = (const float*)d_in[0];   // [32,256,56,56]
    const float* w = (const float*)d_in[1];   // [1,2,3,3]
    float* out = (float*)d_out;               // [32,256,56,56]

    pool_partial<<<(QSPLIT * BATCH * S4) / 256, 256>>>(x);   // 784 blocks
    fused_mid<<<BATCH, 1024>>>(w);                           // 32 blocks
    bcast<<<(BATCH * 32 * S4) / 512, 512>>>(out);            // 1568 blocks
}